// round 12
// baseline (speedup 1.0000x reference)
#include <cuda_runtime.h>
#include <cuda_fp16.h>
#include <cuda_fp8.h>
#include <cstdint>

// Fused gate_up GEMM + SiLU*mul + per-128-group fp8-e4m3 quant via mma.sync
// (HMMA m16n8k16 fp16/fp32-acc). fp16 2-way split, W pre-scaled x64:
// gate_up*64 = x0w0 + x1w0 + x0w1 (dropped x1w1 ~2^-22). Epilogue descales.
//
// R12 = R11 (CTA 64x256, 2x4 warps, K=32 2-stage SW64, 2 CTAs/SM) plus:
//  (a) co-resident-CTA de-phasing: odd wave-slot CTAs spin ~1200cyc once so
//      the two CTAs' barrier-aligned ldsm heads interleave instead of
//      colliding (R11 profile: tensor=76.4% with issue=18% => dependency
//      bubbles, not occupancy).
//  (b) vectorized split kernels (16B stores per plane).
//
// Output layout (float32): [T*I fp8-rounded values] ++ [T*(I/128) scales]

#define T_DIM 4096
#define H_DIM 4096
#define I_DIM 14336
#define NGROUPS (I_DIM / 128)

static const size_t XS_PLANE = (size_t)T_DIM * H_DIM;
static const size_t WS_PLANE = (size_t)2 * I_DIM * H_DIM;

__device__ __align__(16) __half g_xs[2ull * 4096ull * 4096ull];   //  64 MB
__device__ __align__(16) __half g_ws[2ull * 28672ull * 4096ull];  // 448 MB
__device__ int g_probe;

__device__ __forceinline__ uint32_t h2bits(__half2 h) {
    return *reinterpret_cast<uint32_t*>(&h);
}

// ---------------------------------------------------------------- pre-pass
__global__ __launch_bounds__(256)
void split_x_kernel(const float* __restrict__ src)
{
    const size_t n8 = XS_PLANE / 8;
    size_t i = (size_t)blockIdx.x * blockDim.x + threadIdx.x;
    const size_t stride = (size_t)gridDim.x * blockDim.x;
    const float4* s4 = (const float4*)src;
    uint4* d0 = (uint4*)g_xs;
    uint4* d1 = (uint4*)(g_xs + XS_PLANE);
    for (; i < n8; i += stride) {
        float4 a = s4[2 * i], b = s4[2 * i + 1];
        float f[8] = {a.x, a.y, a.z, a.w, b.x, b.y, b.z, b.w};
        uint32_t r0[4], r1[4];
#pragma unroll
        for (int e = 0; e < 4; ++e) {
            float2 v = make_float2(f[2 * e], f[2 * e + 1]);
            __half2 h0 = __float22half2_rn(v);
            float2 w0 = __half22float2(h0);
            __half2 h1 = __float22half2_rn(make_float2(v.x - w0.x, v.y - w0.y));
            r0[e] = h2bits(h0); r1[e] = h2bits(h1);
        }
        d0[i] = make_uint4(r0[0], r0[1], r0[2], r0[3]);
        d1[i] = make_uint4(r1[0], r1[1], r1[2], r1[3]);
    }
}

__global__ __launch_bounds__(256)
void split_w_kernel(const float* __restrict__ src)
{
    const size_t n8 = WS_PLANE / 8;
    size_t i = (size_t)blockIdx.x * blockDim.x + threadIdx.x;
    const size_t stride = (size_t)gridDim.x * blockDim.x;
    const float4* s4 = (const float4*)src;
    uint4* d0 = (uint4*)g_ws;
    uint4* d1 = (uint4*)(g_ws + WS_PLANE);
    for (; i < n8; i += stride) {
        float4 a = s4[2 * i], b = s4[2 * i + 1];
        float f[8] = {a.x * 64.0f, a.y * 64.0f, a.z * 64.0f, a.w * 64.0f,
                      b.x * 64.0f, b.y * 64.0f, b.z * 64.0f, b.w * 64.0f};
        uint32_t r0[4], r1[4];
#pragma unroll
        for (int e = 0; e < 4; ++e) {
            float2 v = make_float2(f[2 * e], f[2 * e + 1]);
            __half2 h0 = __float22half2_rn(v);
            float2 w0 = __half22float2(h0);
            __half2 h1 = __float22half2_rn(make_float2(v.x - w0.x, v.y - w0.y));
            r0[e] = h2bits(h0); r1[e] = h2bits(h1);
        }
        d0[i] = make_uint4(r0[0], r0[1], r0[2], r0[3]);
        d1[i] = make_uint4(r1[0], r1[1], r1[2], r1[3]);
    }
}

// Tiny alignment kernel so the main GEMM lands in ncu's -s 5 capture slot.
__global__ void probe_kernel()
{
    if (threadIdx.x == 0 && blockIdx.x == 0) g_probe = 1;
}

// ---------------------------------------------------------------- main GEMM
// Stage (K=32): A0|A1 (64x64B = 4KB each) + B0|B1 (256x64B = 16KB each).
#define STG      40960
#define A1_OFF   4096
#define B_OFF    8192
#define BP_OFF   16384                // B1 = B_OFF + BP_OFF
#define SMEM_SZ  (2 * STG)            // 80 KB -> 2 CTAs/SM
#define YS       264

__device__ __forceinline__ uint32_t s2u(const void* p) {
    uint32_t a;
    asm("{ .reg .u64 t; cvta.to.shared.u64 t, %1; cvt.u32.u64 %0, t; }"
        : "=r"(a) : "l"(p));
    return a;
}
__device__ __forceinline__ void cp16(uint32_t s, const void* g) {
    asm volatile("cp.async.cg.shared.global [%0], [%1], 16;"
                 :: "r"(s), "l"(g) : "memory");
}
#define CP_COMMIT() asm volatile("cp.async.commit_group;" ::: "memory")
#define CP_WAIT1()  asm volatile("cp.async.wait_group 1;" ::: "memory")

__device__ __forceinline__ void ldsm4(uint32_t* r, uint32_t addr) {
    asm volatile("ldmatrix.sync.aligned.m8n8.x4.shared.b16 {%0,%1,%2,%3}, [%4];"
                 : "=r"(r[0]), "=r"(r[1]), "=r"(r[2]), "=r"(r[3]) : "r"(addr));
}
__device__ __forceinline__ void mma16816(float* c, const uint32_t* a,
                                         uint32_t b0, uint32_t b1) {
    asm volatile(
        "mma.sync.aligned.m16n8k16.row.col.f32.f16.f16.f32 "
        "{%0,%1,%2,%3}, {%4,%5,%6,%7}, {%8,%9}, {%0,%1,%2,%3};"
        : "+f"(c[0]), "+f"(c[1]), "+f"(c[2]), "+f"(c[3])
        : "r"(a[0]), "r"(a[1]), "r"(a[2]), "r"(a[3]), "r"(b0), "r"(b1));
}

__global__ __launch_bounds__(256, 2)
void mlp_mma_kernel(float* __restrict__ out)
{
    extern __shared__ __align__(1024) char smem[];
    const uint32_t sb = s2u(smem);
    const int tid = threadIdx.x;
    const int lane = tid & 31, wid = tid >> 5;
    const int wm = wid >> 2, wn = wid & 3;       // 2x4 warp grid
    const int row0 = blockIdx.x * 64;
    const int g0   = blockIdx.y * 128;

    // De-phase co-resident CTAs: under the wave placement model, the two
    // CTAs sharing an SM differ in parity of floor(bid/148). Offset one of
    // them by ~half a stage so their barrier/ldsm heads interleave.
    {
        const unsigned bid = blockIdx.x + (unsigned)gridDim.x * blockIdx.y;
        if ((bid / 148u) & 1u) {
            long long t0 = clock64();
            while (clock64() - t0 < 1200) {}
        }
    }

    // ---- producer: 10 x 16B chunks per thread per stage (SW64 rows) ----
    const int kc    = tid & 3;                   // 16B chunk within 64B row
    const int rowid = tid >> 2;                  // 0..63
    const uint32_t swx = (uint32_t)((kc * 16) ^ ((rowid & 6) << 3));

    const __half* gA = g_xs + (size_t)(row0 + rowid) * H_DIM + kc * 8;
    const uint32_t offA = (uint32_t)(rowid * 64) + swx;

    const __half* gB[4];
    uint32_t offB[4];
#pragma unroll
    for (int j = 0; j < 4; ++j) {
        int n = rowid + 64 * j;                  // 0..255
        size_t wr = (n < 128) ? (size_t)(g0 + n)
                              : (size_t)I_DIM + (size_t)g0 + (n - 128);
        gB[j]   = g_ws + wr * H_DIM + kc * 8;
        offB[j] = (uint32_t)(B_OFF + n * 64) + swx;
    }

    auto load_stage = [&](int s, int kt) {
        const uint32_t base = sb + s * STG;
        const int ko = kt * 32;
        cp16(base + offA,          gA + ko);
        cp16(base + A1_OFF + offA, gA + XS_PLANE + ko);
#pragma unroll
        for (int j = 0; j < 4; ++j) {
            cp16(base + offB[j],          gB[j] + ko);
            cp16(base + BP_OFF + offB[j], gB[j] + WS_PLANE + ko);
        }
    };

    // ---- consumer fragment addressing (SW64, 64B rows; verified in R8) ----
    const uint32_t aXor  = (uint32_t)((lane & 6) << 3);
    const uint32_t aCol0 = (uint32_t)((lane >> 4) * 16);
    uint32_t aAddr[2];
#pragma unroll
    for (int ms = 0; ms < 2; ++ms)
        aAddr[ms] = (uint32_t)((wm * 32 + ms * 16 + (lane & 15)) * 64);

    uint32_t bAddr[4];
#pragma unroll
    for (int jj = 0; jj < 4; ++jj) {
        int nloc = wn * 64 + jj * 16 + (lane & 7) + ((lane & 16) >> 1);
        bAddr[jj] = (uint32_t)(nloc * 64);       // (nloc&6)==(lane&6)
    }
    const uint32_t bCol0 = (uint32_t)(((lane >> 3) & 1) * 16);

    float acc[2][8][4];
#pragma unroll
    for (int ms = 0; ms < 2; ++ms)
#pragma unroll
        for (int j = 0; j < 8; ++j)
#pragma unroll
            for (int e = 0; e < 4; ++e) acc[ms][j][e] = 0.0f;

    load_stage(0, 0); CP_COMMIT();
    load_stage(1, 1); CP_COMMIT();

    const int nK = H_DIM / 32;                   // 128 stages
    for (int kt = 0; kt < nK; ++kt) {
        const int s = kt & 1;
        CP_WAIT1();
        __syncthreads();
        const uint32_t sbase = sb + s * STG;

#pragma unroll
        for (int t = 0; t < 2; ++t) {
            uint32_t a0[2][4], a1[2][4];
            const uint32_t ac = (t * 32 + aCol0) ^ aXor;
#pragma unroll
            for (int ms = 0; ms < 2; ++ms) {
                ldsm4(a0[ms], sbase + aAddr[ms] + ac);
                ldsm4(a1[ms], sbase + A1_OFF + aAddr[ms] + ac);
            }
#pragma unroll
            for (int jj = 0; jj < 4; ++jj) {
                uint32_t b0[4], b1[4];
                const uint32_t bc = (t * 32 + bCol0) ^ aXor;
                ldsm4(b0, sbase + B_OFF + bAddr[jj] + bc);
                ldsm4(b1, sbase + B_OFF + BP_OFF + bAddr[jj] + bc);
#pragma unroll
                for (int ms = 0; ms < 2; ++ms) {
#pragma unroll
                    for (int h = 0; h < 2; ++h) {
                        float* c = acc[ms][jj * 2 + h];
                        mma16816(c, a0[ms], b0[2 * h], b0[2 * h + 1]); // x0*w0
                        mma16816(c, a1[ms], b0[2 * h], b0[2 * h + 1]); // x1*w0
                        mma16816(c, a0[ms], b1[2 * h], b1[2 * h + 1]); // x0*w1
                    }
                }
            }
        }
        __syncthreads();
        if (kt + 2 < nK) load_stage(s, kt + 2);
        CP_COMMIT();
    }

    // ---- epilogue: stash descaled fp32, then silu*mul + fp8 quant ----
    __syncthreads();
    float* ys = (float*)smem;                    // 64 x YS floats (~67.5 KB)
    const float inv64 = 0.015625f;
#pragma unroll
    for (int ms = 0; ms < 2; ++ms) {
#pragma unroll
        for (int j = 0; j < 8; ++j) {
            const int R = wm * 32 + ms * 16 + (lane >> 2);
            const int C = wn * 64 + j * 8 + (lane & 3) * 2;
            ys[R * YS + C]           = acc[ms][j][0] * inv64;
            ys[R * YS + C + 1]       = acc[ms][j][1] * inv64;
            ys[(R + 8) * YS + C]     = acc[ms][j][2] * inv64;
            ys[(R + 8) * YS + C + 1] = acc[ms][j][3] * inv64;
        }
    }
    __syncthreads();

    float* res = out;
    float* scl = out + (size_t)T_DIM * I_DIM;
#pragma unroll
    for (int rr = 0; rr < 8; ++rr) {
        const int r = wid * 8 + rr;
        const int grow = row0 + r;
        const float* yr = ys + r * YS;
        const int c0 = lane * 4;

        float4 gv = *(const float4*)(yr + c0);
        float4 uv = *(const float4*)(yr + 128 + c0);
        float g4[4] = {gv.x, gv.y, gv.z, gv.w};
        float u4[4] = {uv.x, uv.y, uv.z, uv.w};
        float y[4];
#pragma unroll
        for (int e = 0; e < 4; ++e) {
            float g = g4[e];
            float sg = 1.0f / (1.0f + expf(-g));
            y[e] = g * sg * u4[e];
        }
        float m = fmaxf(fmaxf(fabsf(y[0]), fabsf(y[1])),
                        fmaxf(fabsf(y[2]), fabsf(y[3])));
#pragma unroll
        for (int off = 16; off > 0; off >>= 1)
            m = fmaxf(m, __shfl_xor_sync(0xffffffffu, m, off));
        float amax  = fmaxf(m, 1e-10f);
        float scale = __fdiv_rn(amax, 448.0f);

        float q[4];
#pragma unroll
        for (int e = 0; e < 4; ++e) {
            float qv = __fdiv_rn(y[e], scale);
            qv = fminf(fmaxf(qv, -448.0f), 448.0f);
            __nv_fp8_storage_t b =
                __nv_cvt_float_to_fp8(qv, __NV_SATFINITE, __NV_E4M3);
            __half_raw hr = __nv_cvt_fp8_to_halfraw(b, __NV_E4M3);
            q[e] = __half2float(__half(hr));
        }
        *(float4*)&res[(size_t)grow * I_DIM + g0 + c0] =
            make_float4(q[0], q[1], q[2], q[3]);
        if (lane == 0)
            scl[(size_t)grow * NGROUPS + blockIdx.y] = scale;
    }
}

// ---------------------------------------------------------------- launch
extern "C" void kernel_launch(void* const* d_in, const int* in_sizes, int n_in,
                              void* d_out, int out_size)
{
    const float* x = (const float*)d_in[0];
    const float* W = (const float*)d_in[1];
    float* out = (float*)d_out;

    cudaFuncSetAttribute(mlp_mma_kernel,
                         cudaFuncAttributeMaxDynamicSharedMemorySize, SMEM_SZ);

    // Period-6 launch pattern keeps the GEMM in ncu's "-s 5" capture slot.
    split_x_kernel<<<2048, 256>>>(x);                        // pos 0
    split_w_kernel<<<8192, 256>>>(W);                        // pos 1
    probe_kernel<<<1, 32>>>();                               // pos 2
    dim3 grid(T_DIM / 64, I_DIM / 128);                      // (64, 112)
    mlp_mma_kernel<<<grid, 256, SMEM_SZ>>>(out);             // pos 3
    probe_kernel<<<1, 32>>>();                               // pos 4
    probe_kernel<<<1, 32>>>();                               // pos 5
}

// round 14
// speedup vs baseline: 1.0009x; 1.0009x over previous
#include <cuda_runtime.h>
#include <cuda_fp16.h>
#include <cuda_fp8.h>
#include <cstdint>

// Fused gate_up GEMM + SiLU*mul + per-128-group fp8-e4m3 quant via mma.sync
// (HMMA m16n8k16 fp16/fp32-acc). fp16 2-way split, W pre-scaled x64:
// gate_up*64 = x0w0 + x1w0 + x0w1 (dropped x1w1 ~2^-22). Epilogue descales.
//
// R14 = R11 (best passing: CTA 64x256, 2x4 warps, K=32 2-stage SW64,
// 2 CTAs/SM) + ONE delta: odd-wn warps visit B column-blocks in rotated
// order {2,3,0,1}. Per-block accumulators => bit-identical numerics; warps'
// ldsm/MMA bursts de-align so dependency heads are covered. R13's unsafe
// load hoist (data race: stage overwritten while other warps still read it)
// is REVERTED -- the two-barrier stage recycle from R11 is restored.
//
// Output layout (float32): [T*I fp8-rounded values] ++ [T*(I/128) scales]

#define T_DIM 4096
#define H_DIM 4096
#define I_DIM 14336
#define NGROUPS (I_DIM / 128)

static const size_t XS_PLANE = (size_t)T_DIM * H_DIM;
static const size_t WS_PLANE = (size_t)2 * I_DIM * H_DIM;

__device__ __align__(16) __half g_xs[2ull * 4096ull * 4096ull];   //  64 MB
__device__ __align__(16) __half g_ws[2ull * 28672ull * 4096ull];  // 448 MB
__device__ int g_probe;

__device__ __forceinline__ uint32_t h2bits(__half2 h) {
    return *reinterpret_cast<uint32_t*>(&h);
}

// ---------------------------------------------------------------- pre-pass
__global__ __launch_bounds__(256)
void split_x_kernel(const float* __restrict__ src)
{
    const size_t n8 = XS_PLANE / 8;
    size_t i = (size_t)blockIdx.x * blockDim.x + threadIdx.x;
    const size_t stride = (size_t)gridDim.x * blockDim.x;
    const float4* s4 = (const float4*)src;
    uint4* d0 = (uint4*)g_xs;
    uint4* d1 = (uint4*)(g_xs + XS_PLANE);
    for (; i < n8; i += stride) {
        float4 a = s4[2 * i], b = s4[2 * i + 1];
        float f[8] = {a.x, a.y, a.z, a.w, b.x, b.y, b.z, b.w};
        uint32_t r0[4], r1[4];
#pragma unroll
        for (int e = 0; e < 4; ++e) {
            float2 v = make_float2(f[2 * e], f[2 * e + 1]);
            __half2 h0 = __float22half2_rn(v);
            float2 w0 = __half22float2(h0);
            __half2 h1 = __float22half2_rn(make_float2(v.x - w0.x, v.y - w0.y));
            r0[e] = h2bits(h0); r1[e] = h2bits(h1);
        }
        d0[i] = make_uint4(r0[0], r0[1], r0[2], r0[3]);
        d1[i] = make_uint4(r1[0], r1[1], r1[2], r1[3]);
    }
}

__global__ __launch_bounds__(256)
void split_w_kernel(const float* __restrict__ src)
{
    const size_t n8 = WS_PLANE / 8;
    size_t i = (size_t)blockIdx.x * blockDim.x + threadIdx.x;
    const size_t stride = (size_t)gridDim.x * blockDim.x;
    const float4* s4 = (const float4*)src;
    uint4* d0 = (uint4*)g_ws;
    uint4* d1 = (uint4*)(g_ws + WS_PLANE);
    for (; i < n8; i += stride) {
        float4 a = s4[2 * i], b = s4[2 * i + 1];
        float f[8] = {a.x * 64.0f, a.y * 64.0f, a.z * 64.0f, a.w * 64.0f,
                      b.x * 64.0f, b.y * 64.0f, b.z * 64.0f, b.w * 64.0f};
        uint32_t r0[4], r1[4];
#pragma unroll
        for (int e = 0; e < 4; ++e) {
            float2 v = make_float2(f[2 * e], f[2 * e + 1]);
            __half2 h0 = __float22half2_rn(v);
            float2 w0 = __half22float2(h0);
            __half2 h1 = __float22half2_rn(make_float2(v.x - w0.x, v.y - w0.y));
            r0[e] = h2bits(h0); r1[e] = h2bits(h1);
        }
        d0[i] = make_uint4(r0[0], r0[1], r0[2], r0[3]);
        d1[i] = make_uint4(r1[0], r1[1], r1[2], r1[3]);
    }
}

// Tiny alignment kernel so the main GEMM lands in ncu's -s 5 capture slot.
__global__ void probe_kernel()
{
    if (threadIdx.x == 0 && blockIdx.x == 0) g_probe = 1;
}

// ---------------------------------------------------------------- main GEMM
// Stage (K=32): A0|A1 (64x64B = 4KB each) + B0|B1 (256x64B = 16KB each).
#define STG      40960
#define A1_OFF   4096
#define B_OFF    8192
#define BP_OFF   16384                // B1 = B_OFF + BP_OFF
#define SMEM_SZ  (2 * STG)            // 80 KB -> 2 CTAs/SM
#define YS       264

__device__ __forceinline__ uint32_t s2u(const void* p) {
    uint32_t a;
    asm("{ .reg .u64 t; cvta.to.shared.u64 t, %1; cvt.u32.u64 %0, t; }"
        : "=r"(a) : "l"(p));
    return a;
}
__device__ __forceinline__ void cp16(uint32_t s, const void* g) {
    asm volatile("cp.async.cg.shared.global [%0], [%1], 16;"
                 :: "r"(s), "l"(g) : "memory");
}
#define CP_COMMIT() asm volatile("cp.async.commit_group;" ::: "memory")
#define CP_WAIT1()  asm volatile("cp.async.wait_group 1;" ::: "memory")

__device__ __forceinline__ void ldsm4(uint32_t* r, uint32_t addr) {
    asm volatile("ldmatrix.sync.aligned.m8n8.x4.shared.b16 {%0,%1,%2,%3}, [%4];"
                 : "=r"(r[0]), "=r"(r[1]), "=r"(r[2]), "=r"(r[3]) : "r"(addr));
}
__device__ __forceinline__ void mma16816(float* c, const uint32_t* a,
                                         uint32_t b0, uint32_t b1) {
    asm volatile(
        "mma.sync.aligned.m16n8k16.row.col.f32.f16.f16.f32 "
        "{%0,%1,%2,%3}, {%4,%5,%6,%7}, {%8,%9}, {%0,%1,%2,%3};"
        : "+f"(c[0]), "+f"(c[1]), "+f"(c[2]), "+f"(c[3])
        : "r"(a[0]), "r"(a[1]), "r"(a[2]), "r"(a[3]), "r"(b0), "r"(b1));
}

__global__ __launch_bounds__(256, 2)
void mlp_mma_kernel(float* __restrict__ out)
{
    extern __shared__ __align__(1024) char smem[];
    const uint32_t sb = s2u(smem);
    const int tid = threadIdx.x;
    const int lane = tid & 31, wid = tid >> 5;
    const int wm = wid >> 2, wn = wid & 3;       // 2x4 warp grid
    const int row0 = blockIdx.x * 64;
    const int g0   = blockIdx.y * 128;

    // jj-rotation: odd-wn warps visit B column-blocks in order {2,3,0,1}.
    // Accumulators are per-block, so numerics are bit-identical; only the
    // epilogue column mapping uses rot.
    const int rot = (wn & 1) * 2;

    // ---- producer: 10 x 16B chunks per thread per stage (SW64 rows) ----
    const int kc    = tid & 3;                   // 16B chunk within 64B row
    const int rowid = tid >> 2;                  // 0..63
    const uint32_t swx = (uint32_t)((kc * 16) ^ ((rowid & 6) << 3));

    const __half* gA = g_xs + (size_t)(row0 + rowid) * H_DIM + kc * 8;
    const uint32_t offA = (uint32_t)(rowid * 64) + swx;

    const __half* gB[4];
    uint32_t offB[4];
#pragma unroll
    for (int j = 0; j < 4; ++j) {
        int n = rowid + 64 * j;                  // 0..255
        size_t wr = (n < 128) ? (size_t)(g0 + n)
                              : (size_t)I_DIM + (size_t)g0 + (n - 128);
        gB[j]   = g_ws + wr * H_DIM + kc * 8;
        offB[j] = (uint32_t)(B_OFF + n * 64) + swx;
    }

    auto load_stage = [&](int s, int kt) {
        const uint32_t base = sb + s * STG;
        const int ko = kt * 32;
        cp16(base + offA,          gA + ko);
        cp16(base + A1_OFF + offA, gA + XS_PLANE + ko);
#pragma unroll
        for (int j = 0; j < 4; ++j) {
            cp16(base + offB[j],          gB[j] + ko);
            cp16(base + BP_OFF + offB[j], gB[j] + WS_PLANE + ko);
        }
    };

    // ---- consumer fragment addressing (SW64, 64B rows; verified in R8) ----
    const uint32_t aXor  = (uint32_t)((lane & 6) << 3);
    const uint32_t aCol0 = (uint32_t)((lane >> 4) * 16);
    uint32_t aAddr[2];
#pragma unroll
    for (int ms = 0; ms < 2; ++ms)
        aAddr[ms] = (uint32_t)((wm * 32 + ms * 16 + (lane & 15)) * 64);

    // bP[i] = address of the i-th block THIS warp visits (physical block
    // (i+rot)&3). (nloc&6)==(lane&6) independent of block -> aXor valid.
    uint32_t bP[4];
#pragma unroll
    for (int i = 0; i < 4; ++i) {
        int jj = (i + rot) & 3;
        int nloc = wn * 64 + jj * 16 + (lane & 7) + ((lane & 16) >> 1);
        bP[i] = (uint32_t)(nloc * 64);
    }
    const uint32_t bCol0 = (uint32_t)(((lane >> 3) & 1) * 16);

    float acc[2][8][4];                          // [ms][i*2+h][e], i = visit order
#pragma unroll
    for (int ms = 0; ms < 2; ++ms)
#pragma unroll
        for (int j = 0; j < 8; ++j)
#pragma unroll
            for (int e = 0; e < 4; ++e) acc[ms][j][e] = 0.0f;

    load_stage(0, 0); CP_COMMIT();
    load_stage(1, 1); CP_COMMIT();

    const int nK = H_DIM / 32;                   // 128 stages
    for (int kt = 0; kt < nK; ++kt) {
        const int s = kt & 1;
        CP_WAIT1();
        __syncthreads();
        const uint32_t sbase = sb + s * STG;

#pragma unroll
        for (int t = 0; t < 2; ++t) {
            uint32_t a0[2][4], a1[2][4];
            const uint32_t ac = (t * 32 + aCol0) ^ aXor;
#pragma unroll
            for (int ms = 0; ms < 2; ++ms) {
                ldsm4(a0[ms], sbase + aAddr[ms] + ac);
                ldsm4(a1[ms], sbase + A1_OFF + aAddr[ms] + ac);
            }
#pragma unroll
            for (int i = 0; i < 4; ++i) {
                uint32_t b0[4], b1[4];
                const uint32_t bc = (t * 32 + bCol0) ^ aXor;
                ldsm4(b0, sbase + B_OFF + bP[i] + bc);
                ldsm4(b1, sbase + B_OFF + BP_OFF + bP[i] + bc);
#pragma unroll
                for (int ms = 0; ms < 2; ++ms) {
#pragma unroll
                    for (int h = 0; h < 2; ++h) {
                        float* c = acc[ms][i * 2 + h];
                        mma16816(c, a0[ms], b0[2 * h], b0[2 * h + 1]); // x0*w0
                        mma16816(c, a1[ms], b0[2 * h], b0[2 * h + 1]); // x1*w0
                        mma16816(c, a0[ms], b1[2 * h], b1[2 * h + 1]); // x0*w1
                    }
                }
            }
        }
        // SAFE stage recycle (R11): barrier ensures ALL warps finished
        // reading stage s before it is overwritten.
        __syncthreads();
        if (kt + 2 < nK) load_stage(s, kt + 2);
        CP_COMMIT();
    }

    // ---- epilogue: stash descaled fp32, then silu*mul + fp8 quant ----
    __syncthreads();
    float* ys = (float*)smem;                    // 64 x YS floats (~67.5 KB)
    const float inv64 = 0.015625f;
#pragma unroll
    for (int ms = 0; ms < 2; ++ms) {
#pragma unroll
        for (int j = 0; j < 8; ++j) {
            const int R = wm * 32 + ms * 16 + (lane >> 2);
            // visit index i = j>>1 maps to physical block (i+rot)&3
            const int C = wn * 64 + (((j >> 1) + rot) & 3) * 16
                        + (j & 1) * 8 + (lane & 3) * 2;
            ys[R * YS + C]           = acc[ms][j][0] * inv64;
            ys[R * YS + C + 1]       = acc[ms][j][1] * inv64;
            ys[(R + 8) * YS + C]     = acc[ms][j][2] * inv64;
            ys[(R + 8) * YS + C + 1] = acc[ms][j][3] * inv64;
        }
    }
    __syncthreads();

    float* res = out;
    float* scl = out + (size_t)T_DIM * I_DIM;
#pragma unroll
    for (int rr = 0; rr < 8; ++rr) {
        const int r = wid * 8 + rr;
        const int grow = row0 + r;
        const float* yr = ys + r * YS;
        const int c0 = lane * 4;

        float4 gv = *(const float4*)(yr + c0);
        float4 uv = *(const float4*)(yr + 128 + c0);
        float g4[4] = {gv.x, gv.y, gv.z, gv.w};
        float u4[4] = {uv.x, uv.y, uv.z, uv.w};
        float y[4];
#pragma unroll
        for (int e = 0; e < 4; ++e) {
            float g = g4[e];
            float sg = 1.0f / (1.0f + expf(-g));
            y[e] = g * sg * u4[e];
        }
        float m = fmaxf(fmaxf(fabsf(y[0]), fabsf(y[1])),
                        fmaxf(fabsf(y[2]), fabsf(y[3])));
#pragma unroll
        for (int off = 16; off > 0; off >>= 1)
            m = fmaxf(m, __shfl_xor_sync(0xffffffffu, m, off));
        float amax  = fmaxf(m, 1e-10f);
        float scale = __fdiv_rn(amax, 448.0f);

        float q[4];
#pragma unroll
        for (int e = 0; e < 4; ++e) {
            float qv = __fdiv_rn(y[e], scale);
            qv = fminf(fmaxf(qv, -448.0f), 448.0f);
            __nv_fp8_storage_t b =
                __nv_cvt_float_to_fp8(qv, __NV_SATFINITE, __NV_E4M3);
            __half_raw hr = __nv_cvt_fp8_to_halfraw(b, __NV_E4M3);
            q[e] = __half2float(__half(hr));
        }
        *(float4*)&res[(size_t)grow * I_DIM + g0 + c0] =
            make_float4(q[0], q[1], q[2], q[3]);
        if (lane == 0)
            scl[(size_t)grow * NGROUPS + blockIdx.y] = scale;
    }
}

// ---------------------------------------------------------------- launch
extern "C" void kernel_launch(void* const* d_in, const int* in_sizes, int n_in,
                              void* d_out, int out_size)
{
    const float* x = (const float*)d_in[0];
    const float* W = (const float*)d_in[1];
    float* out = (float*)d_out;

    cudaFuncSetAttribute(mlp_mma_kernel,
                         cudaFuncAttributeMaxDynamicSharedMemorySize, SMEM_SZ);

    // Period-6 launch pattern keeps the GEMM in ncu's "-s 5" capture slot.
    split_x_kernel<<<2048, 256>>>(x);                        // pos 0
    split_w_kernel<<<8192, 256>>>(W);                        // pos 1
    probe_kernel<<<1, 32>>>();                               // pos 2
    dim3 grid(T_DIM / 64, I_DIM / 128);                      // (64, 112)
    mlp_mma_kernel<<<grid, 256, SMEM_SZ>>>(out);             // pos 3
    probe_kernel<<<1, 32>>>();                               // pos 4
    probe_kernel<<<1, 32>>>();                               // pos 5
}

// round 15
// speedup vs baseline: 1.1503x; 1.1493x over previous
#include <cuda_runtime.h>
#include <cuda_fp16.h>
#include <cuda_fp8.h>
#include <cstdint>

// Fused gate_up GEMM + SiLU*mul + per-128-group fp8-e4m3 quant via mma.sync
// (HMMA m16n8k16 fp16/fp32-acc). fp16 2-way split, W pre-scaled x64:
// gate_up*64 = x0w0 + x1w0 + x0w1 (dropped x1w1 ~2^-22). Epilogue descales.
//
// R15: SAME tile/fragments/numerics as R11 (CTA 64x256, 2x4 warps, K=32,
// SW64) but the 2-stage __syncthreads pipeline is replaced by a 4-stage
// mbarrier full/empty ring (cp.async.mbarrier.arrive.noinc). No CTA-wide
// lockstep point remains on the compute path: a warp only blocks if another
// warp is >1 full stage behind, so warps free-run and cover each other's
// ldsm dependency heads (the ~830cyc/stage bubble R10-R14 could not remove).
// 4 x 40KB buffers -> 164KB smem, 1 CTA/SM.
//
// Output layout (float32): [T*I fp8-rounded values] ++ [T*(I/128) scales]

#define T_DIM 4096
#define H_DIM 4096
#define I_DIM 14336
#define NGROUPS (I_DIM / 128)

static const size_t XS_PLANE = (size_t)T_DIM * H_DIM;
static const size_t WS_PLANE = (size_t)2 * I_DIM * H_DIM;

__device__ __align__(16) __half g_xs[2ull * 4096ull * 4096ull];   //  64 MB
__device__ __align__(16) __half g_ws[2ull * 28672ull * 4096ull];  // 448 MB
__device__ int g_probe;

__device__ __forceinline__ uint32_t h2bits(__half2 h) {
    return *reinterpret_cast<uint32_t*>(&h);
}

// ---------------------------------------------------------------- pre-pass
__global__ __launch_bounds__(256)
void split_x_kernel(const float* __restrict__ src)
{
    const size_t n8 = XS_PLANE / 8;
    size_t i = (size_t)blockIdx.x * blockDim.x + threadIdx.x;
    const size_t stride = (size_t)gridDim.x * blockDim.x;
    const float4* s4 = (const float4*)src;
    uint4* d0 = (uint4*)g_xs;
    uint4* d1 = (uint4*)(g_xs + XS_PLANE);
    for (; i < n8; i += stride) {
        float4 a = s4[2 * i], b = s4[2 * i + 1];
        float f[8] = {a.x, a.y, a.z, a.w, b.x, b.y, b.z, b.w};
        uint32_t r0[4], r1[4];
#pragma unroll
        for (int e = 0; e < 4; ++e) {
            float2 v = make_float2(f[2 * e], f[2 * e + 1]);
            __half2 h0 = __float22half2_rn(v);
            float2 w0 = __half22float2(h0);
            __half2 h1 = __float22half2_rn(make_float2(v.x - w0.x, v.y - w0.y));
            r0[e] = h2bits(h0); r1[e] = h2bits(h1);
        }
        d0[i] = make_uint4(r0[0], r0[1], r0[2], r0[3]);
        d1[i] = make_uint4(r1[0], r1[1], r1[2], r1[3]);
    }
}

__global__ __launch_bounds__(256)
void split_w_kernel(const float* __restrict__ src)
{
    const size_t n8 = WS_PLANE / 8;
    size_t i = (size_t)blockIdx.x * blockDim.x + threadIdx.x;
    const size_t stride = (size_t)gridDim.x * blockDim.x;
    const float4* s4 = (const float4*)src;
    uint4* d0 = (uint4*)g_ws;
    uint4* d1 = (uint4*)(g_ws + WS_PLANE);
    for (; i < n8; i += stride) {
        float4 a = s4[2 * i], b = s4[2 * i + 1];
        float f[8] = {a.x * 64.0f, a.y * 64.0f, a.z * 64.0f, a.w * 64.0f,
                      b.x * 64.0f, b.y * 64.0f, b.z * 64.0f, b.w * 64.0f};
        uint32_t r0[4], r1[4];
#pragma unroll
        for (int e = 0; e < 4; ++e) {
            float2 v = make_float2(f[2 * e], f[2 * e + 1]);
            __half2 h0 = __float22half2_rn(v);
            float2 w0 = __half22float2(h0);
            __half2 h1 = __float22half2_rn(make_float2(v.x - w0.x, v.y - w0.y));
            r0[e] = h2bits(h0); r1[e] = h2bits(h1);
        }
        d0[i] = make_uint4(r0[0], r0[1], r0[2], r0[3]);
        d1[i] = make_uint4(r1[0], r1[1], r1[2], r1[3]);
    }
}

// Tiny alignment kernel so the main GEMM lands in ncu's -s 5 capture slot.
__global__ void probe_kernel()
{
    if (threadIdx.x == 0 && blockIdx.x == 0) g_probe = 1;
}

// ---------------------------------------------------------------- main GEMM
// Stage (K=32): A0|A1 (64x64B = 4KB each) + B0|B1 (256x64B = 16KB each).
#define STG      40960
#define A1_OFF   4096
#define B_OFF    8192
#define BP_OFF   16384                // B1 = B_OFF + BP_OFF
#define NSTAGE   4
#define SMEM_SZ  (1024 + NSTAGE * STG)   // 164864 -> 1 CTA/SM
#define YS       264

__device__ __forceinline__ uint32_t s2u(const void* p) {
    uint32_t a;
    asm("{ .reg .u64 t; cvta.to.shared.u64 t, %1; cvt.u32.u64 %0, t; }"
        : "=r"(a) : "l"(p));
    return a;
}
__device__ __forceinline__ void cp16(uint32_t s, const void* g) {
    asm volatile("cp.async.cg.shared.global [%0], [%1], 16;"
                 :: "r"(s), "l"(g) : "memory");
}

#define MBAR_INIT(a, c) \
    asm volatile("mbarrier.init.shared.b64 [%0], %1;" :: "r"(a), "r"(c) : "memory")
#define MBAR_ARRIVE(a) \
    asm volatile("mbarrier.arrive.shared.b64 _, [%0];" :: "r"(a) : "memory")
// Arrive-on when ALL of this thread's prior cp.asyncs complete (.noinc:
// expected count pre-set at init).
#define CP_MBAR_ARRIVE(a) \
    asm volatile("cp.async.mbarrier.arrive.noinc.shared.b64 [%0];" \
                 :: "r"(a) : "memory")
#define MBAR_WAIT(a, p) do {                                                        \
    asm volatile("{\n\t.reg .pred P;\n\t"                                           \
                 "WL_%=:\n\t"                                                       \
                 "mbarrier.try_wait.parity.acquire.cta.shared::cta.b64 P, [%0], %1;\n\t" \
                 "@!P bra WL_%=;\n\t}"                                              \
                 :: "r"(a), "r"(p) : "memory");                                     \
} while (0)

__device__ __forceinline__ void ldsm4(uint32_t* r, uint32_t addr) {
    asm volatile("ldmatrix.sync.aligned.m8n8.x4.shared.b16 {%0,%1,%2,%3}, [%4];"
                 : "=r"(r[0]), "=r"(r[1]), "=r"(r[2]), "=r"(r[3]) : "r"(addr));
}
__device__ __forceinline__ void mma16816(float* c, const uint32_t* a,
                                         uint32_t b0, uint32_t b1) {
    asm volatile(
        "mma.sync.aligned.m16n8k16.row.col.f32.f16.f16.f32 "
        "{%0,%1,%2,%3}, {%4,%5,%6,%7}, {%8,%9}, {%0,%1,%2,%3};"
        : "+f"(c[0]), "+f"(c[1]), "+f"(c[2]), "+f"(c[3])
        : "r"(a[0]), "r"(a[1]), "r"(a[2]), "r"(a[3]), "r"(b0), "r"(b1));
}

__global__ __launch_bounds__(256, 1)
void mlp_mma_kernel(float* __restrict__ out)
{
    extern __shared__ __align__(1024) char smem[];
    const uint32_t sb = s2u(smem);
    const int tid = threadIdx.x;
    const int lane = tid & 31, wid = tid >> 5;
    const int wm = wid >> 2, wn = wid & 3;       // 2x4 warp grid
    const int row0 = blockIdx.x * 64;
    const int g0   = blockIdx.y * 128;

    // mbarriers: full[b] at sb + b*8, empty[b] at sb + 32 + b*8
#define FULLB(b)  (sb + (uint32_t)((b) * 8))
#define EMPTYB(b) (sb + 32u + (uint32_t)((b) * 8))
    if (tid == 0) {
#pragma unroll
        for (int b = 0; b < NSTAGE; ++b) {
            MBAR_INIT(FULLB(b), 256);
            MBAR_INIT(EMPTYB(b), 256);
        }
    }
    __syncthreads();

    // ---- producer: 10 x 16B chunks per thread per stage (SW64 rows) ----
    const int kc    = tid & 3;                   // 16B chunk within 64B row
    const int rowid = tid >> 2;                  // 0..63
    const uint32_t swx = (uint32_t)((kc * 16) ^ ((rowid & 6) << 3));

    const __half* gA = g_xs + (size_t)(row0 + rowid) * H_DIM + kc * 8;
    const uint32_t offA = (uint32_t)(rowid * 64) + swx;

    const __half* gB[4];
    uint32_t offB[4];
#pragma unroll
    for (int j = 0; j < 4; ++j) {
        int n = rowid + 64 * j;                  // 0..255
        size_t wr = (n < 128) ? (size_t)(g0 + n)
                              : (size_t)I_DIM + (size_t)g0 + (n - 128);
        gB[j]   = g_ws + wr * H_DIM + kc * 8;
        offB[j] = (uint32_t)(B_OFF + n * 64) + swx;
    }

    auto load_stage = [&](int b, int kt) {
        const uint32_t base = sb + 1024 + b * STG;
        const int ko = kt * 32;
        cp16(base + offA,          gA + ko);
        cp16(base + A1_OFF + offA, gA + XS_PLANE + ko);
#pragma unroll
        for (int j = 0; j < 4; ++j) {
            cp16(base + offB[j],          gB[j] + ko);
            cp16(base + BP_OFF + offB[j], gB[j] + WS_PLANE + ko);
        }
    };

    // ---- consumer fragment addressing (SW64, 64B rows; verified R8-R14) ----
    const uint32_t aXor  = (uint32_t)((lane & 6) << 3);
    const uint32_t aCol0 = (uint32_t)((lane >> 4) * 16);
    uint32_t aAddr[2];
#pragma unroll
    for (int ms = 0; ms < 2; ++ms)
        aAddr[ms] = (uint32_t)((wm * 32 + ms * 16 + (lane & 15)) * 64);

    uint32_t bAddr[4];
#pragma unroll
    for (int jj = 0; jj < 4; ++jj) {
        int nloc = wn * 64 + jj * 16 + (lane & 7) + ((lane & 16) >> 1);
        bAddr[jj] = (uint32_t)(nloc * 64);       // (nloc&6)==(lane&6)
    }
    const uint32_t bCol0 = (uint32_t)(((lane >> 3) & 1) * 16);

    float acc[2][8][4];
#pragma unroll
    for (int ms = 0; ms < 2; ++ms)
#pragma unroll
        for (int j = 0; j < 8; ++j)
#pragma unroll
            for (int e = 0; e < 4; ++e) acc[ms][j][e] = 0.0f;

    const int nK = H_DIM / 32;                   // 128 stages
    // prologue: stages 0..2 into buffers 0..2 (buffer 3 filled at kt=0)
    load_stage(0, 0); CP_MBAR_ARRIVE(FULLB(0));
    load_stage(1, 1); CP_MBAR_ARRIVE(FULLB(1));
    load_stage(2, 2); CP_MBAR_ARRIVE(FULLB(2));

    for (int kt = 0; kt < nK; ++kt) {
        const int b = kt & 3;
        MBAR_WAIT(FULLB(b), (kt >> 2) & 1);      // stage kt data ready
        const uint32_t sbase = sb + 1024 + b * STG;

#pragma unroll
        for (int t = 0; t < 2; ++t) {
            uint32_t a0[2][4], a1[2][4];
            const uint32_t ac = (t * 32 + aCol0) ^ aXor;
#pragma unroll
            for (int ms = 0; ms < 2; ++ms) {
                ldsm4(a0[ms], sbase + aAddr[ms] + ac);
                ldsm4(a1[ms], sbase + A1_OFF + aAddr[ms] + ac);
            }
#pragma unroll
            for (int jj = 0; jj < 4; ++jj) {
                uint32_t b0[4], b1[4];
                const uint32_t bc = (t * 32 + bCol0) ^ aXor;
                ldsm4(b0, sbase + B_OFF + bAddr[jj] + bc);
                ldsm4(b1, sbase + B_OFF + BP_OFF + bAddr[jj] + bc);
#pragma unroll
                for (int ms = 0; ms < 2; ++ms) {
#pragma unroll
                    for (int h = 0; h < 2; ++h) {
                        float* c = acc[ms][jj * 2 + h];
                        mma16816(c, a0[ms], b0[2 * h], b0[2 * h + 1]); // x0*w0
                        mma16816(c, a1[ms], b0[2 * h], b0[2 * h + 1]); // x1*w0
                        mma16816(c, a0[ms], b1[2 * h], b1[2 * h + 1]); // x0*w1
                    }
                }
            }
        }
        MBAR_ARRIVE(EMPTYB(b));                  // this warp done reading kt

        const int m = kt + 3;                    // next stage to load
        if (m < nK) {
            const int bm = m & 3;
            const int e  = m - 4;                // prior user of buffer bm
            if (e >= 0)                          // kt==0 loads fresh buf 3
                MBAR_WAIT(EMPTYB(bm), (e >> 2) & 1);  // all warps done with e
            load_stage(bm, m);
            CP_MBAR_ARRIVE(FULLB(bm));
        }
    }

    // ---- epilogue: stash descaled fp32, then silu*mul + fp8 quant ----
    __syncthreads();
    float* ys = (float*)(smem + 1024);           // 64 x YS floats (~67.5 KB)
    const float inv64 = 0.015625f;
#pragma unroll
    for (int ms = 0; ms < 2; ++ms) {
#pragma unroll
        for (int j = 0; j < 8; ++j) {
            const int R = wm * 32 + ms * 16 + (lane >> 2);
            const int C = wn * 64 + j * 8 + (lane & 3) * 2;
            ys[R * YS + C]           = acc[ms][j][0] * inv64;
            ys[R * YS + C + 1]       = acc[ms][j][1] * inv64;
            ys[(R + 8) * YS + C]     = acc[ms][j][2] * inv64;
            ys[(R + 8) * YS + C + 1] = acc[ms][j][3] * inv64;
        }
    }
    __syncthreads();

    float* res = out;
    float* scl = out + (size_t)T_DIM * I_DIM;
#pragma unroll
    for (int rr = 0; rr < 8; ++rr) {
        const int r = wid * 8 + rr;
        const int grow = row0 + r;
        const float* yr = ys + r * YS;
        const int c0 = lane * 4;

        float4 gv = *(const float4*)(yr + c0);
        float4 uv = *(const float4*)(yr + 128 + c0);
        float g4[4] = {gv.x, gv.y, gv.z, gv.w};
        float u4[4] = {uv.x, uv.y, uv.z, uv.w};
        float y[4];
#pragma unroll
        for (int e = 0; e < 4; ++e) {
            float g = g4[e];
            float sg = 1.0f / (1.0f + expf(-g));
            y[e] = g * sg * u4[e];
        }
        float m = fmaxf(fmaxf(fabsf(y[0]), fabsf(y[1])),
                        fmaxf(fabsf(y[2]), fabsf(y[3])));
#pragma unroll
        for (int off = 16; off > 0; off >>= 1)
            m = fmaxf(m, __shfl_xor_sync(0xffffffffu, m, off));
        float amax  = fmaxf(m, 1e-10f);
        float scale = __fdiv_rn(amax, 448.0f);

        float q[4];
#pragma unroll
        for (int e = 0; e < 4; ++e) {
            float qv = __fdiv_rn(y[e], scale);
            qv = fminf(fmaxf(qv, -448.0f), 448.0f);
            __nv_fp8_storage_t b =
                __nv_cvt_float_to_fp8(qv, __NV_SATFINITE, __NV_E4M3);
            __half_raw hr = __nv_cvt_fp8_to_halfraw(b, __NV_E4M3);
            q[e] = __half2float(__half(hr));
        }
        *(float4*)&res[(size_t)grow * I_DIM + g0 + c0] =
            make_float4(q[0], q[1], q[2], q[3]);
        if (lane == 0)
            scl[(size_t)grow * NGROUPS + blockIdx.y] = scale;
    }
}

// ---------------------------------------------------------------- launch
extern "C" void kernel_launch(void* const* d_in, const int* in_sizes, int n_in,
                              void* d_out, int out_size)
{
    const float* x = (const float*)d_in[0];
    const float* W = (const float*)d_in[1];
    float* out = (float*)d_out;

    cudaFuncSetAttribute(mlp_mma_kernel,
                         cudaFuncAttributeMaxDynamicSharedMemorySize, SMEM_SZ);

    // Period-6 launch pattern keeps the GEMM in ncu's "-s 5" capture slot.
    split_x_kernel<<<2048, 256>>>(x);                        // pos 0
    split_w_kernel<<<8192, 256>>>(W);                        // pos 1
    probe_kernel<<<1, 32>>>();                               // pos 2
    dim3 grid(T_DIM / 64, I_DIM / 128);                      // (64, 112)
    mlp_mma_kernel<<<grid, 256, SMEM_SZ>>>(out);             // pos 3
    probe_kernel<<<1, 32>>>();                               // pos 4
    probe_kernel<<<1, 32>>>();                               // pos 5
}